// round 5
// baseline (speedup 1.0000x reference)
#include <cuda_runtime.h>
#include <cstdint>

#define NT      8192
#define DIMD    1024
#define HID     4096
#define NE      8
#define NSLOTS  (NT * 2)

#define BM 128
#define BN 128
#define BK 16

// ---------------- device scratch (static: no allocation allowed) ----------------
__device__ float g_h[(size_t)NSLOTS * HID];     // 256 MB: relu(x@w1+b1) per slot
__device__ float g_y[(size_t)NSLOTS * DIMD];    //  64 MB: (h@w2+b2) per slot
__device__ float g_gate[NSLOTS];
__device__ int   g_list[NE * NSLOTS];           // per-expert slot lists
__device__ int   g_cnt[NE];
__device__ float g_ent;
__device__ float g_imp[NE];

// ---------------- helpers ----------------
__device__ __forceinline__ float to_tf32(float x) {
    unsigned r;
    asm("cvt.rna.tf32.f32 %0, %1;" : "=r"(r) : "f"(x));
    return __uint_as_float(r);
}

__device__ __forceinline__ void mma8(float* c, const float* a, const float* b) {
    asm volatile(
        "mma.sync.aligned.m16n8k8.row.col.f32.tf32.tf32.f32 "
        "{%0,%1,%2,%3}, {%4,%5,%6,%7}, {%8,%9}, {%0,%1,%2,%3};\n"
        : "+f"(c[0]), "+f"(c[1]), "+f"(c[2]), "+f"(c[3])
        : "r"(__float_as_uint(a[0])), "r"(__float_as_uint(a[1])),
          "r"(__float_as_uint(a[2])), "r"(__float_as_uint(a[3])),
          "r"(__float_as_uint(b[0])), "r"(__float_as_uint(b[1])));
}

// ---------------- kernels ----------------
__global__ void reset_k() {
    int i = threadIdx.x;
    if (i < NE) { g_cnt[i] = 0; g_imp[i] = 0.f; }
    if (i == 0) g_ent = 0.f;
}

// One warp per token: router logits, full softmax (entropy/importance),
// top-2 gates, atomic scatter into expert lists.
__global__ void router_k(const float* __restrict__ x,
                         const float* __restrict__ rw,
                         const float* __restrict__ rb) {
    __shared__ float s_ent[8];
    __shared__ float s_p[8][NE];
    int warp = threadIdx.x >> 5, lane = threadIdx.x & 31;
    int t = (blockIdx.x << 3) + warp;
    const float* xr = x + (size_t)t * DIMD;

    float acc[NE];
#pragma unroll
    for (int e = 0; e < NE; e++) acc[e] = 0.f;

#pragma unroll 4
    for (int i = 0; i < DIMD / 32; i++) {
        int k = (i << 5) + lane;
        float xv = xr[k];
        const float4* w4 = (const float4*)(rw + (size_t)k * NE);
        float4 w0 = w4[0], w1 = w4[1];
        acc[0] += xv * w0.x; acc[1] += xv * w0.y;
        acc[2] += xv * w0.z; acc[3] += xv * w0.w;
        acc[4] += xv * w1.x; acc[5] += xv * w1.y;
        acc[6] += xv * w1.z; acc[7] += xv * w1.w;
    }
#pragma unroll
    for (int e = 0; e < NE; e++) {
#pragma unroll
        for (int o = 16; o > 0; o >>= 1)
            acc[e] += __shfl_xor_sync(0xffffffffu, acc[e], o);
    }

    if (lane == 0) {
        float lg[NE], p[NE];
        float mx = -1e30f;
#pragma unroll
        for (int e = 0; e < NE; e++) { lg[e] = acc[e] + rb[e]; mx = fmaxf(mx, lg[e]); }
        float se = 0.f;
#pragma unroll
        for (int e = 0; e < NE; e++) { p[e] = expf(lg[e] - mx); se += p[e]; }
        float inv = 1.f / se, ent = 0.f;
#pragma unroll
        for (int e = 0; e < NE; e++) {
            p[e] *= inv;
            ent -= p[e] * logf(fmaxf(p[e], 1e-8f));
        }
        // top-2 (first index wins ties, matching lax.top_k)
        int e0 = 0;
#pragma unroll
        for (int e = 1; e < NE; e++) if (lg[e] > lg[e0]) e0 = e;
        int e1 = (e0 == 0) ? 1 : 0;
#pragma unroll
        for (int e = 0; e < NE; e++) if (e != e0 && lg[e] > lg[e1]) e1 = e;
        float d = expf(lg[e1] - lg[e0]);       // <= 1, stable
        float g0 = 1.f / (1.f + d);
        float g1 = d / (1.f + d);

        int p0 = atomicAdd(&g_cnt[e0], 1);
        g_list[e0 * NSLOTS + p0] = t * 2;
        g_gate[t * 2] = g0;
        int p1 = atomicAdd(&g_cnt[e1], 1);
        g_list[e1 * NSLOTS + p1] = t * 2 + 1;
        g_gate[t * 2 + 1] = g1;

        s_ent[warp] = ent;
#pragma unroll
        for (int e = 0; e < NE; e++) s_p[warp][e] = p[e];
    }
    __syncthreads();
    if (threadIdx.x < NE) {
        float s = 0.f;
#pragma unroll
        for (int w = 0; w < 8; w++) s += s_p[w][threadIdx.x];
        atomicAdd(&g_imp[threadIdx.x], s);
    }
    if (threadIdx.x == 0) {
        float s = 0.f;
#pragma unroll
        for (int w = 0; w < 8; w++) s += s_ent[w];
        atomicAdd(&g_ent, s);
    }
}

__global__ void finalize_k(float* __restrict__ out, int n) {
    float ent = g_ent / (float)NT;
    float lb = 0.f;
#pragma unroll
    for (int e = 0; e < NE; e++) {
        float d = g_imp[e] / (float)NT - (1.f / NE);
        lb += d * d;
    }
    lb /= (float)NE;
    out[n - 2] = ent;
    out[n - 1] = lb;
}

// Gather-GEMM over an expert's slot list.
// PHASE 1: A = x (row = slot>>1), C = g_h, relu(+b1)
// PHASE 2: A = g_h (row = slot), C = g_y, +b2
template <int PHASE>
__global__ __launch_bounds__(256) void moe_gemm(const float* __restrict__ Xin,
                                                const float* __restrict__ Wt,
                                                const float* __restrict__ bias,
                                                int K, int N) {
    const int e = blockIdx.z;
    const int cnt = g_cnt[e];
    const int m0 = blockIdx.x * BM;
    if (m0 >= cnt) return;
    const int bn = blockIdx.y * BN;

    const float* A = (PHASE == 1) ? Xin : g_h;
    float* C = (PHASE == 1) ? g_h : g_y;
    const int SRC_SHIFT = (PHASE == 1) ? 1 : 0;

    __shared__ float sA[2][2048];   // fragment-permuted: [ki][mi][lane][4]
    __shared__ float sB[2][2048];   // fragment-permuted: [ki][ni][lane][2]

    const int tid = threadIdx.x;
    const int lane = tid & 31;
    const int warp = tid >> 5;
    const int wr = warp >> 2;   // 0..1  -> warp_m = wr*64
    const int wc = warp & 3;    // 0..3  -> warp_n = wc*32

    const int* list = g_list + e * NSLOTS + m0;

    // A: 2 float4 per thread, rows fixed across K loop
    const float* aptr[2];
#pragma unroll
    for (int j = 0; j < 2; j++) {
        int idx = tid + j * 256;
        int m = idx >> 2, c4 = idx & 3;
        int srow = (m0 + m < cnt) ? (list[m] >> SRC_SHIFT) : 0;
        aptr[j] = A + (size_t)srow * K + (c4 << 2);
    }
    // B: 2 float4 per thread
    const float* bptr[2];
#pragma unroll
    for (int j = 0; j < 2; j++) {
        int idx = tid + j * 256;
        int kr = idx >> 5, n4 = idx & 31;
        bptr[j] = Wt + (size_t)e * K * N + (size_t)kr * N + bn + (n4 << 2);
    }

    float acc[4][4][4];
#pragma unroll
    for (int i = 0; i < 4; i++)
#pragma unroll
        for (int j = 0; j < 4; j++)
#pragma unroll
            for (int r = 0; r < 4; r++) acc[i][j][r] = 0.f;

    float4 aL[2], bL[2];
    const int KT = K / BK;

    // prefetch k-tile 0
#pragma unroll
    for (int j = 0; j < 2; j++) {
        aL[j] = *(const float4*)(aptr[j]);
        bL[j] = *(const float4*)(bptr[j]);
    }

    for (int kt = 0; kt < KT; kt++) {
        const int s = kt & 1;
        // store current tile to smem in fragment-permuted layout (+tf32 round)
#pragma unroll
        for (int j = 0; j < 2; j++) {
            int idx = tid + j * 256;
            {
                int m = idx >> 2, c4 = idx & 3;
                int mi = m >> 4;
                float v[4] = {aL[j].x, aL[j].y, aL[j].z, aL[j].w};
#pragma unroll
                for (int tt = 0; tt < 4; tt++) {
                    int k = (c4 << 2) + tt;
                    int ki = k >> 3;
                    int ln = ((m & 7) << 2) | (k & 3);
                    int rg = (((k & 7) >> 2) << 1) | ((m & 15) >> 3);
                    sA[s][(((((ki << 3) + mi) << 5) | ln) << 2) | rg] = to_tf32(v[tt]);
                }
            }
            {
                int kr = idx >> 5, n4 = idx & 31;
                int ki = kr >> 3;
                float v[4] = {bL[j].x, bL[j].y, bL[j].z, bL[j].w};
#pragma unroll
                for (int tt = 0; tt < 4; tt++) {
                    int n = (n4 << 2) + tt;
                    int ni = n >> 3;
                    int ln = ((n & 7) << 2) | (kr & 3);
                    int rg = (kr & 7) >> 2;
                    sB[s][(((((ki << 4) + ni) << 5) | ln) << 1) | rg] = to_tf32(v[tt]);
                }
            }
        }
        __syncthreads();

        // prefetch next tile while computing
        if (kt + 1 < KT) {
#pragma unroll
            for (int j = 0; j < 2; j++) {
                aL[j] = *(const float4*)(aptr[j] + (size_t)(kt + 1) * BK);
                bL[j] = *(const float4*)(bptr[j] + (size_t)(kt + 1) * BK * N);
            }
        }

        // compute on stage s
#pragma unroll
        for (int ki = 0; ki < 2; ki++) {
            float af[4][4], bf[4][2];
#pragma unroll
            for (int mi = 0; mi < 4; mi++) {
                float4 tv = *(const float4*)&sA[s][((((ki << 3) + (wr << 2) + mi) << 5) + lane) << 2];
                af[mi][0] = tv.x; af[mi][1] = tv.y; af[mi][2] = tv.z; af[mi][3] = tv.w;
            }
#pragma unroll
            for (int ni = 0; ni < 4; ni++) {
                float2 tv = *(const float2*)&sB[s][((((ki << 4) + (wc << 2) + ni) << 5) + lane) << 1];
                bf[ni][0] = tv.x; bf[ni][1] = tv.y;
            }
#pragma unroll
            for (int mi = 0; mi < 4; mi++)
#pragma unroll
                for (int ni = 0; ni < 4; ni++)
                    mma8(acc[mi][ni], af[mi], bf[ni]);
        }
    }

    // epilogue: +bias, optional relu, scatter rows to C[slot]
    const int g = lane >> 2;
    const int cbase = bn + (wc << 5) + ((lane & 3) << 1);
#pragma unroll
    for (int mi = 0; mi < 4; mi++) {
#pragma unroll
        for (int half = 0; half < 2; half++) {
            int lr = (wr << 6) + (mi << 4) + g + (half << 3);
            if (m0 + lr < cnt) {
                int slot = list[lr];
                float* crow = C + (size_t)slot * N;
#pragma unroll
                for (int ni = 0; ni < 4; ni++) {
                    int col = cbase + (ni << 3);
                    float bv0 = bias[(size_t)e * N + col];
                    float bv1 = bias[(size_t)e * N + col + 1];
                    float v0 = acc[mi][ni][half * 2 + 0] + bv0;
                    float v1 = acc[mi][ni][half * 2 + 1] + bv1;
                    if (PHASE == 1) { v0 = fmaxf(v0, 0.f); v1 = fmaxf(v1, 0.f); }
                    *(float2*)(crow + col) = make_float2(v0, v1);
                }
            }
        }
    }
}

__global__ void combine_k(float* __restrict__ out) {
    int id = blockIdx.x * blockDim.x + threadIdx.x;   // NT*256 threads
    int t = id >> 8;
    int c = (id & 255) << 2;
    float g0 = g_gate[t * 2], g1 = g_gate[t * 2 + 1];
    float4 a = *(const float4*)&g_y[(size_t)(t * 2) * DIMD + c];
    float4 b = *(const float4*)&g_y[(size_t)(t * 2 + 1) * DIMD + c];
    float4 o;
    o.x = g0 * a.x + g1 * b.x;
    o.y = g0 * a.y + g1 * b.y;
    o.z = g0 * a.z + g1 * b.z;
    o.w = g0 * a.w + g1 * b.w;
    *(float4*)&out[(size_t)t * DIMD + c] = o;
}

// ---------------- launch ----------------
extern "C" void kernel_launch(void* const* d_in, const int* in_sizes, int n_in,
                              void* d_out, int out_size) {
    const float* x  = (const float*)d_in[0];
    const float* rw = (const float*)d_in[1];
    const float* rb = (const float*)d_in[2];
    const float* w1 = (const float*)d_in[3];
    const float* b1 = (const float*)d_in[4];
    const float* w2 = (const float*)d_in[5];
    const float* b2 = (const float*)d_in[6];
    float* out = (float*)d_out;

    reset_k<<<1, 32>>>();
    router_k<<<NT / 8, 256>>>(x, rw, rb);
    finalize_k<<<1, 1>>>(out, out_size);

    dim3 grid1(NSLOTS / BM, HID / BN, NE);
    moe_gemm<1><<<grid1, 256>>>(x, w1, b1, DIMD, HID);

    dim3 grid2(NSLOTS / BM, DIMD / BN, NE);
    moe_gemm<2><<<grid2, 256>>>(nullptr, w2, b2, HID, DIMD);

    combine_k<<<NT, 256>>>(out);
}

// round 6
// speedup vs baseline: 1.0019x; 1.0019x over previous
#include <cuda_runtime.h>
#include <cstdint>

#define NT      8192
#define DIMD    1024
#define HID     4096
#define NE      8
#define NSLOTS  (NT * 2)

#define BM 128
#define BN 128
#define BK 16

// ---------------- device scratch (static: no allocation allowed) ----------------
__device__ float g_h[(size_t)NSLOTS * HID];     // 256 MB: relu(x@w1+b1) per slot
__device__ float g_y[(size_t)NSLOTS * DIMD];    //  64 MB: (h@w2+b2) per slot
__device__ float g_gate[NSLOTS];
__device__ int   g_list[NE * NSLOTS];           // per-expert slot lists
__device__ int   g_cnt[NE];
__device__ float g_ent;
__device__ float g_imp[NE];

// ---------------- helpers ----------------
__device__ __forceinline__ float to_tf32(float x) {
    unsigned r;
    asm("cvt.rna.tf32.f32 %0, %1;" : "=r"(r) : "f"(x));
    return __uint_as_float(r);
}

__device__ __forceinline__ void mma8(float* c, const float* a, const float* b) {
    asm volatile(
        "mma.sync.aligned.m16n8k8.row.col.f32.tf32.tf32.f32 "
        "{%0,%1,%2,%3}, {%4,%5,%6,%7}, {%8,%9}, {%0,%1,%2,%3};\n"
        : "+f"(c[0]), "+f"(c[1]), "+f"(c[2]), "+f"(c[3])
        : "r"(__float_as_uint(a[0])), "r"(__float_as_uint(a[1])),
          "r"(__float_as_uint(a[2])), "r"(__float_as_uint(a[3])),
          "r"(__float_as_uint(b[0])), "r"(__float_as_uint(b[1])));
}

// ---------------- kernels ----------------
__global__ void reset_k() {
    int i = threadIdx.x;
    if (i < NE) { g_cnt[i] = 0; g_imp[i] = 0.f; }
    if (i == 0) g_ent = 0.f;
}

// One warp per token: router logits, full softmax (entropy/importance),
// top-2 gates, atomic scatter into expert lists.
__global__ void router_k(const float* __restrict__ x,
                         const float* __restrict__ rw,
                         const float* __restrict__ rb) {
    __shared__ float s_ent[8];
    __shared__ float s_p[8][NE];
    int warp = threadIdx.x >> 5, lane = threadIdx.x & 31;
    int t = (blockIdx.x << 3) + warp;
    const float* xr = x + (size_t)t * DIMD;

    float acc[NE];
#pragma unroll
    for (int e = 0; e < NE; e++) acc[e] = 0.f;

#pragma unroll 4
    for (int i = 0; i < DIMD / 32; i++) {
        int k = (i << 5) + lane;
        float xv = xr[k];
        const float4* w4 = (const float4*)(rw + (size_t)k * NE);
        float4 w0 = w4[0], w1 = w4[1];
        acc[0] += xv * w0.x; acc[1] += xv * w0.y;
        acc[2] += xv * w0.z; acc[3] += xv * w0.w;
        acc[4] += xv * w1.x; acc[5] += xv * w1.y;
        acc[6] += xv * w1.z; acc[7] += xv * w1.w;
    }
#pragma unroll
    for (int e = 0; e < NE; e++) {
#pragma unroll
        for (int o = 16; o > 0; o >>= 1)
            acc[e] += __shfl_xor_sync(0xffffffffu, acc[e], o);
    }

    if (lane == 0) {
        float lg[NE], p[NE];
        float mx = -1e30f;
#pragma unroll
        for (int e = 0; e < NE; e++) { lg[e] = acc[e] + rb[e]; mx = fmaxf(mx, lg[e]); }
        float se = 0.f;
#pragma unroll
        for (int e = 0; e < NE; e++) { p[e] = expf(lg[e] - mx); se += p[e]; }
        float inv = 1.f / se, ent = 0.f;
#pragma unroll
        for (int e = 0; e < NE; e++) {
            p[e] *= inv;
            ent -= p[e] * logf(fmaxf(p[e], 1e-8f));
        }
        // top-2 (first index wins ties, matching lax.top_k)
        int e0 = 0;
#pragma unroll
        for (int e = 1; e < NE; e++) if (lg[e] > lg[e0]) e0 = e;
        int e1 = (e0 == 0) ? 1 : 0;
#pragma unroll
        for (int e = 0; e < NE; e++) if (e != e0 && lg[e] > lg[e1]) e1 = e;
        float d = expf(lg[e1] - lg[e0]);       // <= 1, stable
        float g0 = 1.f / (1.f + d);
        float g1 = d / (1.f + d);

        int p0 = atomicAdd(&g_cnt[e0], 1);
        g_list[e0 * NSLOTS + p0] = t * 2;
        g_gate[t * 2] = g0;
        int p1 = atomicAdd(&g_cnt[e1], 1);
        g_list[e1 * NSLOTS + p1] = t * 2 + 1;
        g_gate[t * 2 + 1] = g1;

        s_ent[warp] = ent;
#pragma unroll
        for (int e = 0; e < NE; e++) s_p[warp][e] = p[e];
    }
    __syncthreads();
    if (threadIdx.x < NE) {
        float s = 0.f;
#pragma unroll
        for (int w = 0; w < 8; w++) s += s_p[w][threadIdx.x];
        atomicAdd(&g_imp[threadIdx.x], s);
    }
    if (threadIdx.x == 0) {
        float s = 0.f;
#pragma unroll
        for (int w = 0; w < 8; w++) s += s_ent[w];
        atomicAdd(&g_ent, s);
    }
}

__global__ void finalize_k(float* __restrict__ out, int n) {
    float ent = g_ent / (float)NT;
    float lb = 0.f;
#pragma unroll
    for (int e = 0; e < NE; e++) {
        float d = g_imp[e] / (float)NT - (1.f / NE);
        lb += d * d;
    }
    lb /= (float)NE;
    out[n - 2] = ent;
    out[n - 1] = lb;
}

// Gather-GEMM over an expert's slot list.
// PHASE 1: A = x (row = slot>>1), C = g_h, relu(+b1)
// PHASE 2: A = g_h (row = slot), C = g_y, +b2
template <int PHASE>
__global__ __launch_bounds__(256) void moe_gemm(const float* __restrict__ Xin,
                                                const float* __restrict__ Wt,
                                                const float* __restrict__ bias,
                                                int K, int N) {
    const int e = blockIdx.z;
    const int cnt = g_cnt[e];
    const int m0 = blockIdx.x * BM;
    if (m0 >= cnt) return;
    const int bn = blockIdx.y * BN;

    const float* A = (PHASE == 1) ? Xin : g_h;
    float* C = (PHASE == 1) ? g_h : g_y;
    const int SRC_SHIFT = (PHASE == 1) ? 1 : 0;

    __shared__ float sA[2][2048];   // fragment-permuted: [ki][mi][lane][4]
    __shared__ float sB[2][2048];   // fragment-permuted: [ki][ni][lane][2]

    const int tid = threadIdx.x;
    const int lane = tid & 31;
    const int warp = tid >> 5;
    const int wr = warp >> 2;   // 0..1  -> warp_m = wr*64
    const int wc = warp & 3;    // 0..3  -> warp_n = wc*32

    const int* list = g_list + e * NSLOTS + m0;

    // A: 2 float4 per thread, rows fixed across K loop
    const float* aptr[2];
#pragma unroll
    for (int j = 0; j < 2; j++) {
        int idx = tid + j * 256;
        int m = idx >> 2, c4 = idx & 3;
        int srow = (m0 + m < cnt) ? (list[m] >> SRC_SHIFT) : 0;
        aptr[j] = A + (size_t)srow * K + (c4 << 2);
    }
    // B: 2 float4 per thread
    const float* bptr[2];
#pragma unroll
    for (int j = 0; j < 2; j++) {
        int idx = tid + j * 256;
        int kr = idx >> 5, n4 = idx & 31;
        bptr[j] = Wt + (size_t)e * K * N + (size_t)kr * N + bn + (n4 << 2);
    }

    float acc[4][4][4];
#pragma unroll
    for (int i = 0; i < 4; i++)
#pragma unroll
        for (int j = 0; j < 4; j++)
#pragma unroll
            for (int r = 0; r < 4; r++) acc[i][j][r] = 0.f;

    float4 aL[2], bL[2];
    const int KT = K / BK;

    // prefetch k-tile 0
#pragma unroll
    for (int j = 0; j < 2; j++) {
        aL[j] = *(const float4*)(aptr[j]);
        bL[j] = *(const float4*)(bptr[j]);
    }

    for (int kt = 0; kt < KT; kt++) {
        const int s = kt & 1;
        // store current tile to smem in fragment-permuted layout (+tf32 round)
#pragma unroll
        for (int j = 0; j < 2; j++) {
            int idx = tid + j * 256;
            {
                int m = idx >> 2, c4 = idx & 3;
                int mi = m >> 4;
                float v[4] = {aL[j].x, aL[j].y, aL[j].z, aL[j].w};
#pragma unroll
                for (int tt = 0; tt < 4; tt++) {
                    int k = (c4 << 2) + tt;
                    int ki = k >> 3;
                    int ln = ((m & 7) << 2) | (k & 3);
                    int rg = (((k & 7) >> 2) << 1) | ((m & 15) >> 3);
                    sA[s][(((((ki << 3) + mi) << 5) | ln) << 2) | rg] = to_tf32(v[tt]);
                }
            }
            {
                int kr = idx >> 5, n4 = idx & 31;
                int ki = kr >> 3;
                float v[4] = {bL[j].x, bL[j].y, bL[j].z, bL[j].w};
#pragma unroll
                for (int tt = 0; tt < 4; tt++) {
                    int n = (n4 << 2) + tt;
                    int ni = n >> 3;
                    int ln = ((n & 7) << 2) | (kr & 3);
                    int rg = (kr & 7) >> 2;
                    sB[s][(((((ki << 4) + ni) << 5) | ln) << 1) | rg] = to_tf32(v[tt]);
                }
            }
        }
        __syncthreads();

        // prefetch next tile while computing
        if (kt + 1 < KT) {
#pragma unroll
            for (int j = 0; j < 2; j++) {
                aL[j] = *(const float4*)(aptr[j] + (size_t)(kt + 1) * BK);
                bL[j] = *(const float4*)(bptr[j] + (size_t)(kt + 1) * BK * N);
            }
        }

        // compute on stage s
#pragma unroll
        for (int ki = 0; ki < 2; ki++) {
            float af[4][4], bf[4][2];
#pragma unroll
            for (int mi = 0; mi < 4; mi++) {
                float4 tv = *(const float4*)&sA[s][((((ki << 3) + (wr << 2) + mi) << 5) + lane) << 2];
                af[mi][0] = tv.x; af[mi][1] = tv.y; af[mi][2] = tv.z; af[mi][3] = tv.w;
            }
#pragma unroll
            for (int ni = 0; ni < 4; ni++) {
                float2 tv = *(const float2*)&sB[s][((((ki << 4) + (wc << 2) + ni) << 5) + lane) << 1];
                bf[ni][0] = tv.x; bf[ni][1] = tv.y;
            }
#pragma unroll
            for (int mi = 0; mi < 4; mi++)
#pragma unroll
                for (int ni = 0; ni < 4; ni++)
                    mma8(acc[mi][ni], af[mi], bf[ni]);
        }
    }

    // epilogue: +bias, optional relu, scatter rows to C[slot]
    const int g = lane >> 2;
    const int cbase = bn + (wc << 5) + ((lane & 3) << 1);
#pragma unroll
    for (int mi = 0; mi < 4; mi++) {
#pragma unroll
        for (int half = 0; half < 2; half++) {
            int lr = (wr << 6) + (mi << 4) + g + (half << 3);
            if (m0 + lr < cnt) {
                int slot = list[lr];
                float* crow = C + (size_t)slot * N;
#pragma unroll
                for (int ni = 0; ni < 4; ni++) {
                    int col = cbase + (ni << 3);
                    float bv0 = bias[(size_t)e * N + col];
                    float bv1 = bias[(size_t)e * N + col + 1];
                    float v0 = acc[mi][ni][half * 2 + 0] + bv0;
                    float v1 = acc[mi][ni][half * 2 + 1] + bv1;
                    if (PHASE == 1) { v0 = fmaxf(v0, 0.f); v1 = fmaxf(v1, 0.f); }
                    *(float2*)(crow + col) = make_float2(v0, v1);
                }
            }
        }
    }
}

__global__ void combine_k(float* __restrict__ out) {
    int id = blockIdx.x * blockDim.x + threadIdx.x;   // NT*256 threads
    int t = id >> 8;
    int c = (id & 255) << 2;
    float g0 = g_gate[t * 2], g1 = g_gate[t * 2 + 1];
    float4 a = *(const float4*)&g_y[(size_t)(t * 2) * DIMD + c];
    float4 b = *(const float4*)&g_y[(size_t)(t * 2 + 1) * DIMD + c];
    float4 o;
    o.x = g0 * a.x + g1 * b.x;
    o.y = g0 * a.y + g1 * b.y;
    o.z = g0 * a.z + g1 * b.z;
    o.w = g0 * a.w + g1 * b.w;
    *(float4*)&out[(size_t)t * DIMD + c] = o;
}

// ---------------- launch ----------------
extern "C" void kernel_launch(void* const* d_in, const int* in_sizes, int n_in,
                              void* d_out, int out_size) {
    const float* x  = (const float*)d_in[0];
    const float* rw = (const float*)d_in[1];
    const float* rb = (const float*)d_in[2];
    const float* w1 = (const float*)d_in[3];
    const float* b1 = (const float*)d_in[4];
    const float* w2 = (const float*)d_in[5];
    const float* b2 = (const float*)d_in[6];
    float* out = (float*)d_out;

    reset_k<<<1, 32>>>();
    router_k<<<NT / 8, 256>>>(x, rw, rb);
    finalize_k<<<1, 1>>>(out, out_size);

    dim3 grid1(NSLOTS / BM, HID / BN, NE);
    moe_gemm<1><<<grid1, 256>>>(x, w1, b1, DIMD, HID);

    dim3 grid2(NSLOTS / BM, DIMD / BN, NE);
    moe_gemm<2><<<grid2, 256>>>(nullptr, w2, b2, HID, DIMD);

    combine_k<<<NT, 256>>>(out);
}

// round 17
// speedup vs baseline: 2.3482x; 2.3438x over previous
#include <cuda_runtime.h>
#include <cstdint>

#define NT      8192
#define DIMD    1024
#define HID     4096
#define NE      8
#define TOPK    2
#define NSLOTS  (NT * 2)

#define BM 128
#define BN 128
#define BK 16

// ---------------- device scratch (static: no allocation allowed) ----------------
__device__ float g_h[(size_t)NSLOTS * HID];     // 256 MB: relu(x@w1+b1) per slot
__device__ float g_y[(size_t)NSLOTS * DIMD];    //  64 MB: (h@w2+b2) per slot
__device__ float g_gate[NSLOTS];
__device__ int   g_list[NE * NSLOTS];           // per-expert slot lists
__device__ int   g_cnt[NE];
__device__ float g_ent;
__device__ float g_imp[NE];

// ---------------- helpers ----------------
__device__ __forceinline__ float to_tf32(float x) {
    unsigned r;
    asm("cvt.rna.tf32.f32 %0, %1;" : "=r"(r) : "f"(x));
    return __uint_as_float(r);
}

__device__ __forceinline__ void mma8(float* c, const float* a, const float* b) {
    asm volatile(
        "mma.sync.aligned.m16n8k8.row.col.f32.tf32.tf32.f32 "
        "{%0,%1,%2,%3}, {%4,%5,%6,%7}, {%8,%9}, {%0,%1,%2,%3};\n"
        : "+f"(c[0]), "+f"(c[1]), "+f"(c[2]), "+f"(c[3])
        : "r"(__float_as_uint(a[0])), "r"(__float_as_uint(a[1])),
          "r"(__float_as_uint(a[2])), "r"(__float_as_uint(a[3])),
          "r"(__float_as_uint(b[0])), "r"(__float_as_uint(b[1])));
}

// ---------------- kernels ----------------
__global__ void reset_k() {
    int i = threadIdx.x;
    if (i < NE) { g_cnt[i] = 0; g_imp[i] = 0.f; }
    if (i == 0) g_ent = 0.f;
}

// One warp per token: router logits, full softmax (entropy/importance),
// top-2 gates, atomic scatter into expert lists.
__global__ void router_k(const float* __restrict__ x,
                         const float* __restrict__ rw,
                         const float* __restrict__ rb) {
    __shared__ float s_ent[8];
    __shared__ float s_p[8][NE];
    int warp = threadIdx.x >> 5, lane = threadIdx.x & 31;
    int t = (blockIdx.x << 3) + warp;
    const float* xr = x + (size_t)t * DIMD;

    float acc[NE];
#pragma unroll
    for (int e = 0; e < NE; e++) acc[e] = 0.f;

#pragma unroll 4
    for (int i = 0; i < DIMD / 32; i++) {
        int k = (i << 5) + lane;
        float xv = xr[k];
        const float4* w4 = (const float4*)(rw + (size_t)k * NE);
        float4 w0 = w4[0], w1 = w4[1];
        acc[0] += xv * w0.x; acc[1] += xv * w0.y;
        acc[2] += xv * w0.z; acc[3] += xv * w0.w;
        acc[4] += xv * w1.x; acc[5] += xv * w1.y;
        acc[6] += xv * w1.z; acc[7] += xv * w1.w;
    }
#pragma unroll
    for (int e = 0; e < NE; e++) {
#pragma unroll
        for (int o = 16; o > 0; o >>= 1)
            acc[e] += __shfl_xor_sync(0xffffffffu, acc[e], o);
    }

    if (lane == 0) {
        float lg[NE], p[NE];
        float mx = -1e30f;
#pragma unroll
        for (int e = 0; e < NE; e++) { lg[e] = acc[e] + rb[e]; mx = fmaxf(mx, lg[e]); }
        float se = 0.f;
#pragma unroll
        for (int e = 0; e < NE; e++) { p[e] = expf(lg[e] - mx); se += p[e]; }
        float inv = 1.f / se, ent = 0.f;
#pragma unroll
        for (int e = 0; e < NE; e++) {
            p[e] *= inv;
            ent -= p[e] * logf(fmaxf(p[e], 1e-8f));
        }
        // top-2 (first index wins ties, matching lax.top_k)
        int e0 = 0;
#pragma unroll
        for (int e = 1; e < NE; e++) if (lg[e] > lg[e0]) e0 = e;
        int e1 = (e0 == 0) ? 1 : 0;
#pragma unroll
        for (int e = 0; e < NE; e++) if (e != e0 && lg[e] > lg[e1]) e1 = e;
        float d = expf(lg[e1] - lg[e0]);       // <= 1, stable
        float g0 = 1.f / (1.f + d);
        float g1 = d / (1.f + d);

        int p0 = atomicAdd(&g_cnt[e0], 1);
        g_list[e0 * NSLOTS + p0] = t * 2;
        g_gate[t * 2] = g0;
        int p1 = atomicAdd(&g_cnt[e1], 1);
        g_list[e1 * NSLOTS + p1] = t * 2 + 1;
        g_gate[t * 2 + 1] = g1;

        s_ent[warp] = ent;
#pragma unroll
        for (int e = 0; e < NE; e++) s_p[warp][e] = p[e];
    }
    __syncthreads();
    if (threadIdx.x < NE) {
        float s = 0.f;
#pragma unroll
        for (int w = 0; w < 8; w++) s += s_p[w][threadIdx.x];
        atomicAdd(&g_imp[threadIdx.x], s);
    }
    if (threadIdx.x == 0) {
        float s = 0.f;
#pragma unroll
        for (int w = 0; w < 8; w++) s += s_ent[w];
        atomicAdd(&g_ent, s);
    }
}

__global__ void finalize_k(float* __restrict__ out, int n) {
    float ent = g_ent / (float)NT;
    float lb = 0.f;
#pragma unroll
    for (int e = 0; e < NE; e++) {
        float d = g_imp[e] / (float)NT - (1.f / NE);
        lb += d * d;
    }
    lb /= (float)NE;
    out[n - 2] = ent;
    out[n - 1] = lb;
}

// Gather-GEMM over an expert's slot list.  (structure identical to the passing R6
// kernel; ONLY the shared-memory layout changed: XOR-swizzled, conflict-free, and
// the producer now stores with STS.128 instead of 16 conflicted scalar STS.)
//   sA: logical (m,k) -> float4 word  m*4 + ((k>>2) ^ (m&3)), elem k&3
//   sB: logical (k,n) -> float4 word  k*32 + ((n>>2) ^ ((k&3)*2)), elem n&3
// PHASE 1: A = x (row = slot>>1), C = g_h, relu(+b1)
// PHASE 2: A = g_h (row = slot), C = g_y, +b2
template <int PHASE>
__global__ __launch_bounds__(256) void moe_gemm(const float* __restrict__ Xin,
                                                const float* __restrict__ Wt,
                                                const float* __restrict__ bias,
                                                int K, int N) {
    const int e = blockIdx.z;
    const int cnt = g_cnt[e];
    const int m0 = blockIdx.x * BM;
    if (m0 >= cnt) return;
    const int bn = blockIdx.y * BN;

    const float* A = (PHASE == 1) ? Xin : g_h;
    float* C = (PHASE == 1) ? g_h : g_y;
    const int SRC_SHIFT = (PHASE == 1) ? 1 : 0;

    __shared__ float sA[2][2048];   // 128 rows x 16 k, swizzled float4 granules
    __shared__ float sB[2][2048];   // 16 k-rows x 128 n, swizzled float4 granules

    const int tid = threadIdx.x;
    const int lane = tid & 31;
    const int warp = tid >> 5;
    const int wr = warp >> 2;   // 0..1  -> warp_m = wr*64
    const int wc = warp & 3;    // 0..3  -> warp_n = wc*32
    const int g = lane >> 2;    // 0..7
    const int cc = lane & 3;    // 0..3

    const int* list = g_list + e * NSLOTS + m0;

    // A: 2 float4 per thread, rows fixed across K loop (identical to R6)
    const float* aptr[2];
#pragma unroll
    for (int j = 0; j < 2; j++) {
        int idx = tid + j * 256;
        int m = idx >> 2, c4 = idx & 3;
        int srow = (m0 + m < cnt) ? (list[m] >> SRC_SHIFT) : 0;
        aptr[j] = A + (size_t)srow * K + (c4 << 2);
    }
    // B: 2 float4 per thread (identical to R6)
    const float* bptr[2];
#pragma unroll
    for (int j = 0; j < 2; j++) {
        int idx = tid + j * 256;
        int kr = idx >> 5, n4 = idx & 31;
        bptr[j] = Wt + (size_t)e * K * N + (size_t)kr * N + bn + (n4 << 2);
    }

    float acc[4][4][4];
#pragma unroll
    for (int i = 0; i < 4; i++)
#pragma unroll
        for (int j = 0; j < 4; j++)
#pragma unroll
            for (int r = 0; r < 4; r++) acc[i][j][r] = 0.f;

    float4 aL[2], bL[2];
    const int KT = K / BK;

    // prefetch k-tile 0
#pragma unroll
    for (int j = 0; j < 2; j++) {
        aL[j] = *(const float4*)(aptr[j]);
        bL[j] = *(const float4*)(bptr[j]);
    }

    for (int kt = 0; kt < KT; kt++) {
        const int s = kt & 1;
        // store current tile to swizzled smem (+tf32 round), STS.128 conflict-free
#pragma unroll
        for (int j = 0; j < 2; j++) {
            int idx = tid + j * 256;
            {
                int m = idx >> 2, c4 = idx & 3;
                float4 v = aL[j];
                v.x = to_tf32(v.x); v.y = to_tf32(v.y);
                v.z = to_tf32(v.z); v.w = to_tf32(v.w);
                ((float4*)sA[s])[(m << 2) + (c4 ^ (m & 3))] = v;
            }
            {
                int kr = idx >> 5, n4 = idx & 31;
                float4 v = bL[j];
                v.x = to_tf32(v.x); v.y = to_tf32(v.y);
                v.z = to_tf32(v.z); v.w = to_tf32(v.w);
                ((float4*)sB[s])[(kr << 5) + (n4 ^ ((kr & 3) << 1))] = v;
            }
        }
        __syncthreads();

        // prefetch next tile while computing
        if (kt + 1 < KT) {
#pragma unroll
            for (int j = 0; j < 2; j++) {
                aL[j] = *(const float4*)(aptr[j] + (size_t)(kt + 1) * BK);
                bL[j] = *(const float4*)(bptr[j] + (size_t)(kt + 1) * BK * N);
            }
        }

        // compute on stage s (scalar LDS, all 32 banks covered per instruction)
#pragma unroll
        for (int ki = 0; ki < 2; ki++) {
            float af[4][4], bf[4][2];
#pragma unroll
            for (int mi = 0; mi < 4; mi++) {
                const int r0 = (wr << 6) + (mi << 4) + g;         // a0 row; a1 row = r0+8
                const int swa = r0 & 3;                            // same for r0+8
                const int c0 = ((((ki << 1) + 0) ^ swa) << 2) + cc;  // k = ki*8 + cc
                const int c1 = ((((ki << 1) + 1) ^ swa) << 2) + cc;  // k = ki*8 + 4 + cc
                af[mi][0] = sA[s][(r0 << 4) + c0];
                af[mi][1] = sA[s][((r0 + 8) << 4) + c0];
                af[mi][2] = sA[s][(r0 << 4) + c1];
                af[mi][3] = sA[s][((r0 + 8) << 4) + c1];
            }
#pragma unroll
            for (int ni = 0; ni < 4; ni++) {
                const int nb = (wc << 5) + (ni << 3);              // n block base
                const int col = ((((nb >> 2) + (g >> 2)) ^ (cc << 1)) << 2) + (g & 3);
                const int k0 = (ki << 3) + cc;                     // b0 k; b1 k = k0+4
                bf[ni][0] = sB[s][(k0 << 7) + col];
                bf[ni][1] = sB[s][((k0 + 4) << 7) + col];
            }
#pragma unroll
            for (int mi = 0; mi < 4; mi++)
#pragma unroll
                for (int ni = 0; ni < 4; ni++)
                    mma8(acc[mi][ni], af[mi], bf[ni]);
        }
        __syncthreads();
    }

    // epilogue: +bias, optional relu, scatter rows to C[slot]  (identical to R6)
    const int cbase = bn + (wc << 5) + (cc << 1);
#pragma unroll
    for (int mi = 0; mi < 4; mi++) {
#pragma unroll
        for (int half = 0; half < 2; half++) {
            int lr = (wr << 6) + (mi << 4) + g + (half << 3);
            if (m0 + lr < cnt) {
                int slot = list[lr];
                float* crow = C + (size_t)slot * N;
#pragma unroll
                for (int ni = 0; ni < 4; ni++) {
                    int col = cbase + (ni << 3);
                    float bv0 = bias[(size_t)e * N + col];
                    float bv1 = bias[(size_t)e * N + col + 1];
                    float v0 = acc[mi][ni][half * 2 + 0] + bv0;
                    float v1 = acc[mi][ni][half * 2 + 1] + bv1;
                    if (PHASE == 1) { v0 = fmaxf(v0, 0.f); v1 = fmaxf(v1, 0.f); }
                    *(float2*)(crow + col) = make_float2(v0, v1);
                }
            }
        }
    }
}

__global__ void combine_k(float* __restrict__ out) {
    int id = blockIdx.x * blockDim.x + threadIdx.x;   // NT*256 threads
    int t = id >> 8;
    int c = (id & 255) << 2;
    float g0 = g_gate[t * 2], g1 = g_gate[t * 2 + 1];
    float4 a = *(const float4*)&g_y[(size_t)(t * 2) * DIMD + c];
    float4 b = *(const float4*)&g_y[(size_t)(t * 2 + 1) * DIMD + c];
    float4 o;
    o.x = g0 * a.x + g1 * b.x;
    o.y = g0 * a.y + g1 * b.y;
    o.z = g0 * a.z + g1 * b.z;
    o.w = g0 * a.w + g1 * b.w;
    *(float4*)&out[(size_t)t * DIMD + c] = o;
}

// ---------------- launch ----------------
extern "C" void kernel_launch(void* const* d_in, const int* in_sizes, int n_in,
                              void* d_out, int out_size) {
    const float* x  = (const float*)d_in[0];
    const float* rw = (const float*)d_in[1];
    const float* rb = (const float*)d_in[2];
    const float* w1 = (const float*)d_in[3];
    const float* b1 = (const float*)d_in[4];
    const float* w2 = (const float*)d_in[5];
    const float* b2 = (const float*)d_in[6];
    float* out = (float*)d_out;

    reset_k<<<1, 32>>>();
    router_k<<<NT / 8, 256>>>(x, rw, rb);
    finalize_k<<<1, 1>>>(out, out_size);

    dim3 grid1(NSLOTS / BM, HID / BN, NE);
    moe_gemm<1><<<grid1, 256>>>(x, w1, b1, DIMD, HID);

    dim3 grid2(NSLOTS / BM, DIMD / BN, NE);
    moe_gemm<2><<<grid2, 256>>>(nullptr, w2, b2, HID, DIMD);

    combine_k<<<NT, 256>>>(out);
}